// round 1
// baseline (speedup 1.0000x reference)
#include <cuda_runtime.h>
#include <math.h>

#define CB 2
#define CT 8
#define CHEADS 12
#define CD 768
#define CDF 3072
#define CE 8
#define CN 196
#define CS 1568
#define CBS 3136           // B*S
#define C3D 2304

// ---------------- scratch (device globals; no allocation allowed) ----------------
__device__ float g_patches[CBS*CD];
__device__ float g_x[CBS*CD];
__device__ float g_h[CBS*CD];
__device__ float g_h2[CBS*CD];
__device__ float g_qkv[CBS*C3D];
__device__ float g_att[CBS*CD];
__device__ float g_he[(size_t)CE*CBS*CDF];   // expert hidden, slot-indexed
__device__ float g_moe[(size_t)CE*CBS*CD];   // expert output, slot-indexed
__device__ float g_tproj[CB*CD];
__device__ int   g_counts[CE];
__device__ int   g_tok[CE*CBS];              // slot -> token row
__device__ int   g_slot[CBS*2];              // token -> its 2 slots
__device__ float g_gate[CBS*2];              // token -> its 2 gates

__device__ __forceinline__ float gelu_t(float x){
    return 0.5f*x*(1.0f + tanhf(0.7978845608028654f*(x + 0.044715f*x*x*x)));
}

// ---------------- patchify: video -> [BS, 768] patch vectors ----------------
__global__ __launch_bounds__(256) void patchify_k(const float* __restrict__ video,
                                                  float* __restrict__ out){
    int i = blockIdx.x*256 + threadIdx.x;
    if (i >= CBS*CD) return;
    int r = i / CD, pp = i % CD;
    int b = r / CS, s = r % CS;
    int t = s / CN, pi = s % CN;
    int ph = pi / 14, pw = pi % 14;
    int c = pp >> 8, rem = pp & 255, py = rem >> 4, px = rem & 15;
    size_t vi = ((((size_t)b*CT + t)*3 + c)*224 + (ph*16+py))*224 + (pw*16+px);
    out[i] = video[vi];
}

// ---------------- layernorm (one block per row, 768 cols) ----------------
__global__ __launch_bounds__(256) void ln_k(const float* __restrict__ x,
                                            const float* __restrict__ gs,
                                            const float* __restrict__ gb,
                                            float* __restrict__ out){
    int r = blockIdx.x;
    const float* xr = x + (size_t)r*CD;
    int d = threadIdx.x;
    float v0 = xr[d], v1 = xr[d+256], v2 = xr[d+512];
    float s = v0+v1+v2, sq = v0*v0+v1*v1+v2*v2;
    #pragma unroll
    for (int o=16;o;o>>=1){ s += __shfl_xor_sync(0xffffffffu,s,o); sq += __shfl_xor_sync(0xffffffffu,sq,o); }
    __shared__ float rs[8], rq[8];
    int w = threadIdx.x>>5;
    if ((threadIdx.x&31)==0){ rs[w]=s; rq[w]=sq; }
    __syncthreads();
    float ts=0.f, tq=0.f;
    #pragma unroll
    for (int i=0;i<8;i++){ ts+=rs[i]; tq+=rq[i]; }
    float mean = ts*(1.0f/CD);
    float var  = tq*(1.0f/CD) - mean*mean;
    float rstd = rsqrtf(var + 1e-5f);
    float* orow = out + (size_t)r*CD;
    orow[d]     = (v0-mean)*rstd*gs[d]     + gb[d];
    orow[d+256] = (v1-mean)*rstd*gs[d+256] + gb[d+256];
    orow[d+512] = (v2-mean)*rstd*gs[d+512] + gb[d+512];
}

// ---------------- generic tiled fp32 GEMM: C[M,N] = A[M,K] @ W[K,N] (+bias,+adds,gelu) ----------------
__global__ __launch_bounds__(256) void gemm64(
    int M, int N, int K,
    const float* __restrict__ A,
    const float* __restrict__ W,
    const float* __restrict__ bias,
    const float* __restrict__ addFull,   // optional residual [M,N]
    const float* __restrict__ addRow,    // optional, adds addRow[(row%CS)*N + col]
    float* __restrict__ C, int doGelu)
{
    __shared__ float As[16][65];
    __shared__ float Bs[16][64];
    int n0 = blockIdx.x*64, m0 = blockIdx.y*64;
    int tid = threadIdx.x;
    int tx = tid & 15, ty = tid >> 4;
    int am = tid >> 2, ak = (tid & 3)*4;
    int bk = tid >> 4, bn = (tid & 15)*4;
    float acc[4][4] = {};
    for (int k0 = 0; k0 < K; k0 += 16){
        float4 av;
        int arow = m0 + am;
        if (arow < M) av = *(const float4*)(A + (size_t)arow*K + (k0+ak));
        else          av = make_float4(0.f,0.f,0.f,0.f);
        As[ak+0][am]=av.x; As[ak+1][am]=av.y; As[ak+2][am]=av.z; As[ak+3][am]=av.w;
        *(float4*)&Bs[bk][bn] = *(const float4*)(W + (size_t)(k0+bk)*N + (n0+bn));
        __syncthreads();
        #pragma unroll
        for (int k=0;k<16;k++){
            float a0=As[k][ty*4+0],a1=As[k][ty*4+1],a2=As[k][ty*4+2],a3=As[k][ty*4+3];
            float b0=Bs[k][tx*4+0],b1=Bs[k][tx*4+1],b2=Bs[k][tx*4+2],b3=Bs[k][tx*4+3];
            acc[0][0]+=a0*b0; acc[0][1]+=a0*b1; acc[0][2]+=a0*b2; acc[0][3]+=a0*b3;
            acc[1][0]+=a1*b0; acc[1][1]+=a1*b1; acc[1][2]+=a1*b2; acc[1][3]+=a1*b3;
            acc[2][0]+=a2*b0; acc[2][1]+=a2*b1; acc[2][2]+=a2*b2; acc[2][3]+=a2*b3;
            acc[3][0]+=a3*b0; acc[3][1]+=a3*b1; acc[3][2]+=a3*b2; acc[3][3]+=a3*b3;
        }
        __syncthreads();
    }
    #pragma unroll
    for (int i=0;i<4;i++){
        int row = m0 + ty*4 + i;
        if (row >= M) continue;
        #pragma unroll
        for (int j=0;j<4;j++){
            int col = n0 + tx*4 + j;
            float v = acc[i][j] + bias[col];
            if (addRow)  v += addRow[(size_t)(row % CS)*N + col];
            if (addFull) v += addFull[(size_t)row*N + col];
            if (doGelu)  v = gelu_t(v);
            C[(size_t)row*N + col] = v;
        }
    }
}

// ---------------- expert GEMM (grid.z = expert, count-guarded) ----------------
__global__ __launch_bounds__(256) void gemm64_expert(
    int N, int K,
    const float* __restrict__ A,            // stride K
    const int* __restrict__ tok_of_slot,    // null => A row = e*CBS+m
    const float* __restrict__ Wl, size_t wstride,
    const float* __restrict__ bl, int bstride,
    float* __restrict__ C,                  // row = e*CBS+m, stride N
    const int* __restrict__ counts, int doGelu)
{
    int e = blockIdx.z;
    int Me = counts[e];
    int m0 = blockIdx.y*64;
    if (m0 >= Me) return;
    const float* W = Wl + (size_t)e*wstride;
    const float* bias = bl + (size_t)e*bstride;
    __shared__ float As[16][65];
    __shared__ float Bs[16][64];
    int n0 = blockIdx.x*64;
    int tid = threadIdx.x;
    int tx = tid & 15, ty = tid >> 4;
    int am = tid >> 2, ak = (tid & 3)*4;
    int bk = tid >> 4, bn = (tid & 15)*4;
    int mm = m0 + am;
    bool valid = mm < Me;
    int arow;
    if (tok_of_slot) arow = valid ? tok_of_slot[e*CBS + mm] : 0;
    else             arow = e*CBS + mm;
    float acc[4][4] = {};
    for (int k0 = 0; k0 < K; k0 += 16){
        float4 av;
        if (valid) av = *(const float4*)(A + (size_t)arow*K + (k0+ak));
        else       av = make_float4(0.f,0.f,0.f,0.f);
        As[ak+0][am]=av.x; As[ak+1][am]=av.y; As[ak+2][am]=av.z; As[ak+3][am]=av.w;
        *(float4*)&Bs[bk][bn] = *(const float4*)(W + (size_t)(k0+bk)*N + (n0+bn));
        __syncthreads();
        #pragma unroll
        for (int k=0;k<16;k++){
            float a0=As[k][ty*4+0],a1=As[k][ty*4+1],a2=As[k][ty*4+2],a3=As[k][ty*4+3];
            float b0=Bs[k][tx*4+0],b1=Bs[k][tx*4+1],b2=Bs[k][tx*4+2],b3=Bs[k][tx*4+3];
            acc[0][0]+=a0*b0; acc[0][1]+=a0*b1; acc[0][2]+=a0*b2; acc[0][3]+=a0*b3;
            acc[1][0]+=a1*b0; acc[1][1]+=a1*b1; acc[1][2]+=a1*b2; acc[1][3]+=a1*b3;
            acc[2][0]+=a2*b0; acc[2][1]+=a2*b1; acc[2][2]+=a2*b2; acc[2][3]+=a2*b3;
            acc[3][0]+=a3*b0; acc[3][1]+=a3*b1; acc[3][2]+=a3*b2; acc[3][3]+=a3*b3;
        }
        __syncthreads();
    }
    #pragma unroll
    for (int i=0;i<4;i++){
        int lm = m0 + ty*4 + i;
        if (lm >= Me) continue;
        size_t crow = (size_t)(e*CBS + lm);
        #pragma unroll
        for (int j=0;j<4;j++){
            int col = n0 + tx*4 + j;
            float v = acc[i][j] + bias[col];
            if (doGelu) v = gelu_t(v);
            C[crow*N + col] = v;
        }
    }
}

// ---------------- flash-style attention: 16 queries/block, stream 32-key chunks ----------------
__global__ __launch_bounds__(256) void attn_k(const float* __restrict__ qkv,
                                              const float* __restrict__ tb,   // [HEADS,15] for layer l
                                              float* __restrict__ out){
    const int h = blockIdx.y, b = blockIdx.z;
    const int q0g = blockIdx.x * 16;
    __shared__ float Qs[16][64];
    __shared__ float Ks[32][65];
    __shared__ float Vs[32][64];
    __shared__ float Ps[8][2][32];
    __shared__ float tbs[15];
    int tid = threadIdx.x, lane = tid & 31, w = tid >> 5;
    if (tid < 15) tbs[tid] = tb[h*15 + tid];
    for (int i = tid; i < 16*64; i += 256){
        int qi = i >> 6, d = i & 63;
        Qs[qi][d] = qkv[(size_t)(b*CS + q0g + qi)*C3D + h*64 + d] * 0.125f;
    }
    __syncthreads();
    const int ql0 = w*2, ql1 = w*2+1;
    const int fq0 = (q0g + ql0)/CN, fq1 = (q0g + ql1)/CN;
    float m0=-1e30f, m1=-1e30f, l0=0.f, l1=0.f;
    float o00=0.f,o01=0.f,o10=0.f,o11=0.f;
    for (int c = 0; c < CS/32; c++){
        __syncthreads();
        for (int i = tid; i < 32*64; i += 256){
            int j = i >> 6, d = i & 63;
            size_t base = (size_t)(b*CS + c*32 + j)*C3D + h*64 + d;
            Ks[j][d] = qkv[base + CD];
            Vs[j][d] = qkv[base + 2*CD];
        }
        __syncthreads();
        int key = c*32 + lane;
        int fk = key/CN;
        float s0=0.f, s1=0.f;
        #pragma unroll
        for (int d=0; d<64; d++){
            float kv = Ks[lane][d];
            s0 += Qs[ql0][d]*kv;
            s1 += Qs[ql1][d]*kv;
        }
        s0 += tbs[fq0 - fk + 7];
        s1 += tbs[fq1 - fk + 7];
        float mx0=s0, mx1=s1;
        #pragma unroll
        for (int o=16;o;o>>=1){ mx0=fmaxf(mx0,__shfl_xor_sync(0xffffffffu,mx0,o)); mx1=fmaxf(mx1,__shfl_xor_sync(0xffffffffu,mx1,o)); }
        float mn0 = fmaxf(m0,mx0), mn1 = fmaxf(m1,mx1);
        float p0 = expf(s0-mn0), p1 = expf(s1-mn1);
        float sp0=p0, sp1=p1;
        #pragma unroll
        for (int o=16;o;o>>=1){ sp0+=__shfl_xor_sync(0xffffffffu,sp0,o); sp1+=__shfl_xor_sync(0xffffffffu,sp1,o); }
        float c0 = expf(m0-mn0), c1 = expf(m1-mn1);
        l0 = l0*c0 + sp0;  l1 = l1*c1 + sp1;
        m0 = mn0; m1 = mn1;
        o00*=c0; o01*=c0; o10*=c1; o11*=c1;
        Ps[w][0][lane]=p0; Ps[w][1][lane]=p1;
        __syncwarp();
        #pragma unroll
        for (int j=0;j<32;j++){
            float v0 = Vs[j][2*lane], v1 = Vs[j][2*lane+1];
            float pa = Ps[w][0][j], pb = Ps[w][1][j];
            o00 += pa*v0; o01 += pa*v1; o10 += pb*v0; o11 += pb*v1;
        }
    }
    float inv0 = 1.f/l0, inv1 = 1.f/l1;
    size_t r0 = (size_t)(b*CS + q0g + ql0)*CD + h*64 + 2*lane;
    size_t r1 = (size_t)(b*CS + q0g + ql1)*CD + h*64 + 2*lane;
    out[r0] = o00*inv0; out[r0+1] = o01*inv0;
    out[r1] = o10*inv1; out[r1+1] = o11*inv1;
}

// ---------------- text projection (tiny) ----------------
__global__ __launch_bounds__(256) void textproj_k(const float* __restrict__ ts,
                                                  const float* __restrict__ wt,
                                                  const float* __restrict__ bt,
                                                  float* __restrict__ out){
    int i = blockIdx.x*256 + threadIdx.x;
    if (i >= CB*CD) return;
    int b = i/CD, d = i%CD;
    float a = bt[d];
    for (int k=0;k<CD;k++) a += ts[b*CD+k]*wt[(size_t)k*CD+d];
    out[i] = a;
}

__global__ void zero8_k(int* c){ if (threadIdx.x < CE) c[threadIdx.x] = 0; }

// ---------------- router: logits, top-2, gates, slot assignment ----------------
__global__ __launch_bounds__(256) void router_k(const float* __restrict__ h2,
                                                const float* __restrict__ tproj,
                                                const float* __restrict__ wr,    // [768,8]
                                                int* __restrict__ counts,
                                                int* __restrict__ tok_of_slot,
                                                int* __restrict__ slot_of,
                                                float* __restrict__ gatev){
    int w = threadIdx.x >> 5, lane = threadIdx.x & 31;
    int r = blockIdx.x*8 + w;
    int b = r / CS;
    float acc[8] = {};
    for (int d = lane; d < CD; d += 32){
        float rv = h2[(size_t)r*CD + d] + tproj[b*CD + d];
        #pragma unroll
        for (int e=0;e<8;e++) acc[e] += rv * wr[d*8 + e];
    }
    #pragma unroll
    for (int e=0;e<8;e++)
        #pragma unroll
        for (int o=16;o;o>>=1) acc[e] += __shfl_xor_sync(0xffffffffu, acc[e], o);
    if (lane == 0){
        int i0 = 0; float v0 = acc[0];
        #pragma unroll
        for (int e=1;e<8;e++) if (acc[e] > v0){ v0=acc[e]; i0=e; }
        int i1 = -1; float v1 = -1e30f;
        #pragma unroll
        for (int e=0;e<8;e++) if (e!=i0 && acc[e] > v1){ v1=acc[e]; i1=e; }
        float g0 = 1.f/(1.f + expf(v1 - v0));
        float g1 = 1.f - g0;
        int p0 = atomicAdd(&counts[i0], 1);
        int s0 = i0*CBS + p0;
        tok_of_slot[s0] = r; slot_of[r*2]   = s0; gatev[r*2]   = g0;
        int p1 = atomicAdd(&counts[i1], 1);
        int s1 = i1*CBS + p1;
        tok_of_slot[s1] = r; slot_of[r*2+1] = s1; gatev[r*2+1] = g1;
    }
}

// ---------------- combine: x += gate0*moe[slot0] + gate1*moe[slot1] ----------------
__global__ __launch_bounds__(256) void combine_k(float* __restrict__ x,
                                                 const float* __restrict__ moe,
                                                 const int* __restrict__ slot_of,
                                                 const float* __restrict__ gatev){
    int i = blockIdx.x*256 + threadIdx.x;
    if (i >= CBS*CD) return;
    int r = i / CD, d = i % CD;
    float v = x[i];
    v += gatev[r*2]   * moe[(size_t)slot_of[r*2]*CD   + d];
    v += gatev[r*2+1] * moe[(size_t)slot_of[r*2+1]*CD + d];
    x[i] = v;
}

// =============================== host ===============================
extern "C" void kernel_launch(void* const* d_in, const int* in_sizes, int n_in,
                              void* d_out, int out_size){
    const float* video   = (const float*)d_in[0];
    const float* text    = (const float*)d_in[1];
    const float* patch_w = (const float*)d_in[2];
    const float* patch_b = (const float*)d_in[3];
    const float* pos_emb = (const float*)d_in[4];
    const float* ln1s    = (const float*)d_in[5];
    const float* ln1b    = (const float*)d_in[6];
    const float* wqkv    = (const float*)d_in[7];
    const float* bqkv    = (const float*)d_in[8];
    const float* wo      = (const float*)d_in[9];
    const float* bo      = (const float*)d_in[10];
    const float* tbias   = (const float*)d_in[11];
    const float* ln2s    = (const float*)d_in[12];
    const float* ln2b    = (const float*)d_in[13];
    const float* wtext   = (const float*)d_in[14];
    const float* btext   = (const float*)d_in[15];
    const float* wrouter = (const float*)d_in[16];
    const float* w1      = (const float*)d_in[17];
    const float* b1      = (const float*)d_in[18];
    const float* w2      = (const float*)d_in[19];
    const float* b2      = (const float*)d_in[20];
    const float* lnfs    = (const float*)d_in[21];
    const float* lnfb    = (const float*)d_in[22];

    float *p_patches,*p_x,*p_h,*p_h2,*p_qkv,*p_att,*p_he,*p_moe,*p_tproj,*p_gate;
    int *p_counts,*p_tok,*p_slot;
    cudaGetSymbolAddress((void**)&p_patches, g_patches);
    cudaGetSymbolAddress((void**)&p_x,       g_x);
    cudaGetSymbolAddress((void**)&p_h,       g_h);
    cudaGetSymbolAddress((void**)&p_h2,      g_h2);
    cudaGetSymbolAddress((void**)&p_qkv,     g_qkv);
    cudaGetSymbolAddress((void**)&p_att,     g_att);
    cudaGetSymbolAddress((void**)&p_he,      g_he);
    cudaGetSymbolAddress((void**)&p_moe,     g_moe);
    cudaGetSymbolAddress((void**)&p_tproj,   g_tproj);
    cudaGetSymbolAddress((void**)&p_counts,  g_counts);
    cudaGetSymbolAddress((void**)&p_tok,     g_tok);
    cudaGetSymbolAddress((void**)&p_slot,    g_slot);
    cudaGetSymbolAddress((void**)&p_gate,    g_gate);

    const int EW = (CBS*CD + 255)/256;   // elementwise grid

    // embed
    patchify_k<<<EW,256>>>(video, p_patches);
    gemm64<<<dim3(CD/64, CBS/64),256>>>(CBS, CD, CD, p_patches, patch_w, patch_b,
                                        nullptr, pos_emb, p_x, 0);

    for (int l = 0; l < 4; l++){
        // attention
        ln_k<<<CBS,256>>>(p_x, ln1s + l*CD, ln1b + l*CD, p_h);
        gemm64<<<dim3(C3D/64, CBS/64),256>>>(CBS, C3D, CD, p_h,
                                             wqkv + (size_t)l*CD*C3D, bqkv + l*C3D,
                                             nullptr, nullptr, p_qkv, 0);
        attn_k<<<dim3(CS/16, CHEADS, CB),256>>>(p_qkv, tbias + l*CHEADS*(2*CT-1), p_att);
        gemm64<<<dim3(CD/64, CBS/64),256>>>(CBS, CD, CD, p_att,
                                            wo + (size_t)l*CD*CD, bo + l*CD,
                                            p_x, nullptr, p_x, 0);
        // MoE
        ln_k<<<CBS,256>>>(p_x, ln2s + l*CD, ln2b + l*CD, p_h2);
        textproj_k<<<(CB*CD+255)/256,256>>>(text, wtext + (size_t)l*CD*CD, btext + l*CD, p_tproj);
        zero8_k<<<1,CE>>>(p_counts);
        router_k<<<CBS/8,256>>>(p_h2, p_tproj, wrouter + (size_t)l*CD*CE,
                                p_counts, p_tok, p_slot, p_gate);
        gemm64_expert<<<dim3(CDF/64, CBS/64, CE),256>>>(CDF, CD, p_h2, p_tok,
                                                        w1 + (size_t)l*CE*CD*CDF, (size_t)CD*CDF,
                                                        b1 + (size_t)l*CE*CDF, CDF,
                                                        p_he, p_counts, 1);
        gemm64_expert<<<dim3(CD/64, CBS/64, CE),256>>>(CD, CDF, p_he, nullptr,
                                                       w2 + (size_t)l*CE*CDF*CD, (size_t)CDF*CD,
                                                       b2 + (size_t)l*CE*CD, CD,
                                                       p_moe, p_counts, 0);
        combine_k<<<EW,256>>>(p_x, p_moe, p_slot, p_gate);
    }

    ln_k<<<CBS,256>>>(p_x, lnfs, lnfb, (float*)d_out);
}